// round 16
// baseline (speedup 1.0000x reference)
#include <cuda_runtime.h>
#include <cstdint>

#define B_    8
#define NQ    16384
#define MK    4096
#define CF    256
#define EPSV  1e-8f

// Scratch: per-query 4 candidate indices and 4 weights (3rd weight split
// across the 3rd/4th nearest when plausible fp32 paths disagree).
__device__ int4   g_idx[B_ * NQ];
__device__ float4 g_w[B_ * NQ];

// ---------------- packed f32x2 helpers (Blackwell) ----------------
__device__ __forceinline__ unsigned long long fma2(unsigned long long a,
                                                   unsigned long long b,
                                                   unsigned long long c) {
    unsigned long long d;
    asm("fma.rn.f32x2 %0, %1, %2, %3;" : "=l"(d) : "l"(a), "l"(b), "l"(c));
    return d;
}
__device__ __forceinline__ unsigned long long pack2(float lo, float hi) {
    unsigned long long d;
    asm("mov.b64 %0, {%1, %2};" : "=l"(d) : "f"(lo), "f"(hi));
    return d;
}
__device__ __forceinline__ void unpack2(unsigned long long v, float& lo, float& hi) {
    asm("mov.b64 {%0, %1}, %2;" : "=f"(lo), "=f"(hi) : "l"(v));
}

// ---------------- rounding-path variants ----------------
__device__ __forceinline__ float norm_noFMA(float x, float y, float z) {
    return __fadd_rn(__fadd_rn(__fmul_rn(x, x), __fmul_rn(y, y)), __fmul_rn(z, z));
}
__device__ __forceinline__ float norm_fx(float x, float y, float z) {  // x bare
    return __fmaf_rn(z, z, __fmaf_rn(y, y, __fmul_rn(x, x)));
}
__device__ __forceinline__ float norm_fy(float x, float y, float z) {  // y bare
    return __fmaf_rn(z, z, __fmaf_rn(x, x, __fmul_rn(y, y)));
}
__device__ __forceinline__ float norm_fz(float x, float y, float z) {  // z bare
    return __fmaf_rn(x, x, __fmaf_rn(y, y, __fmul_rn(z, z)));
}

// Primary path (cublas-style): dot = fma(uz,kz, fma(uy,ky, rn(ux*kx)));
// d2 = rn( rn(un+kn) - 2*dot ), norms noFMA.
__device__ __forceinline__ float d2_primary(float ux, float uy, float uz, float un3,
                                            float kx, float ky, float kz, float kn3) {
    float t = __fmaf_rn(uz, kz, __fmaf_rn(uy, ky, __fmul_rn(ux, kx)));
    return __fsub_rn(__fadd_rn(un3, kn3), __fadd_rn(t, t));
}

// ---------------- per-query epilogue (unchanged numerics) ----------------
// primary order + 12-path disagreement hedge; writes g_idx/g_w.
__device__ __forceinline__ void finish_query(
    int b, int q, float ux, float uy, float uz,
    const float* skx, const float* sky, const float* skz, const float* skn,
    float c0, float c1, float c2, float c3, int i0, int i1, int i2, int i3) {

    int fi[4] = { i0, i1, i2, i3 };
    float kxs[4], kys[4], kzs[4], kn3s[4], d2p[4];
    const float un3 = norm_noFMA(ux, uy, uz);
#pragma unroll
    for (int t = 0; t < 4; ++t) {
        kxs[t] = skx[fi[t]]; kys[t] = sky[fi[t]]; kzs[t] = skz[fi[t]];
        kn3s[t] = skn[fi[t]];
        d2p[t] = d2_primary(ux, uy, uz, un3, kxs[t], kys[t], kzs[t], kn3s[t]);
    }
    // stable sort-4 by (primary d2, idx) — matches top_k tie semantics
#define CSWAP(a, b_)                                                        \
    if (d2p[a] > d2p[b_] || (d2p[a] == d2p[b_] && fi[a] > fi[b_])) {        \
        float td = d2p[a]; d2p[a] = d2p[b_]; d2p[b_] = td;                  \
        int ti = fi[a]; fi[a] = fi[b_]; fi[b_] = ti;                        \
        td = kxs[a]; kxs[a] = kxs[b_]; kxs[b_] = td;                        \
        td = kys[a]; kys[a] = kys[b_]; kys[b_] = td;                        \
        td = kzs[a]; kzs[a] = kzs[b_]; kzs[b_] = td;                        \
        td = kn3s[a]; kn3s[a] = kn3s[b_]; kn3s[b_] = td;                    \
    }
    CSWAP(0, 1) CSWAP(2, 3) CSWAP(0, 2) CSWAP(1, 3) CSWAP(1, 2)
#undef CSWAP

    // 12 alternative-path d2 values for the boundary pair (slots 2 and 3)
    const float unx = norm_fx(ux, uy, uz);
    const float uny = norm_fy(ux, uy, uz);
    const float m2x = -2.f * ux, m2y = -2.f * uy, m2z = -2.f * uz;
    float pv[2][12];
#pragma unroll
    for (int t = 0; t < 2; ++t) {
        const float kx = kxs[2 + t], ky = kys[2 + t], kz = kzs[2 + t];
        const float knx = norm_fx(kx, ky, kz);
        const float kny = norm_fy(kx, ky, kz);
        const float kn3 = kn3s[2 + t];
        const float knz = norm_fz(kx, ky, kz);
        const float t1 = __fmaf_rn(uz, kz, __fmaf_rn(uy, ky, __fmul_rn(ux, kx)));
        const float t2 = __fmaf_rn(uz, kz, __fmaf_rn(ux, kx, __fmul_rn(uy, ky)));
        const float t3 = __fadd_rn(__fadd_rn(__fmul_rn(ux, kx), __fmul_rn(uy, ky)),
                                   __fmul_rn(uz, kz));
        const float nn[3] = { __fadd_rn(unx, knx), __fadd_rn(uny, kny),
                              __fadd_rn(norm_noFMA(ux, uy, uz), kn3) };
        const float dd[3] = { __fadd_rn(t1, t1), __fadd_rn(t2, t2),
                              __fadd_rn(t3, t3) };
#pragma unroll
        for (int a = 0; a < 3; ++a)
#pragma unroll
            for (int c = 0; c < 3; ++c)
                pv[t][a * 3 + c] = __fsub_rn(nn[c], dd[a]);
        // fused-chain variants (R1 family) — compare by s (common un offset)
        pv[t][9]  = __fmaf_rn(m2z, kz, __fmaf_rn(m2y, ky, __fmaf_rn(m2x, kx, knz)));
        pv[t][10] = __fmaf_rn(m2x, kx, __fmaf_rn(m2y, ky, __fmaf_rn(m2z, kz, knz)));
        pv[t][11] = __fmaf_rn(m2z, kz, __fmaf_rn(m2y, ky, __fmaf_rn(m2x, kx, kn3)));
    }
    bool hedge = false;
#pragma unroll
    for (int v = 0; v < 12; ++v)
        hedge |= (pv[1][v] < pv[0][v]) ||
                 (pv[1][v] == pv[0][v] && fi[3] < fi[2]);
    // insurance: primary gap below ~0.5 ulp of the cancelling magnitude
    const float gap = d2p[3] - d2p[2];
    hedge |= (gap < __fadd_rn(un3, kn3s[2]) * 3.0e-8f);
    const float p = hedge ? 0.5f : 0.0f;

    const float r0 = __fdiv_rn(1.f, __fadd_rn(d2p[0], EPSV));
    const float r1 = __fdiv_rn(1.f, __fadd_rn(d2p[1], EPSV));
    const float r2 = __fdiv_rn(1.f, __fadd_rn(d2p[2], EPSV));
    const float nrm = __fadd_rn(__fadd_rn(r0, r1), r2);
    const float w2 = __fdiv_rn(r2, nrm);

    const int o = b * NQ + q;
    g_idx[o] = make_int4(fi[0], fi[1], fi[2], fi[3]);
    g_w[o]   = make_float4(__fdiv_rn(r0, nrm), __fdiv_rn(r1, nrm),
                           w2 * (1.f - p), w2 * p);
}

// ---------------- Kernel 1: three_nn, 2 queries per thread ----------------
// grid (NQ/512, B), 256 threads. Each thread scans for queries q and q+256:
// the 4 LDS.128 per iteration feed 8 scores (2x amortization), and the two
// queries' fma2/min chains are independent (2x ILP on the critical path).
extern "C" __global__ void __launch_bounds__(256, 1)
three_nn_k(const float* __restrict__ unknown, const float* __restrict__ known) {
    extern __shared__ float sh[];
    float* skx = sh;
    float* sky = sh + MK;
    float* skz = sh + 2 * MK;
    float* skn = sh + 3 * MK;

    const int b = blockIdx.y;
    const float* kb = known + (size_t)b * MK * 3;
    for (int m = threadIdx.x; m < MK; m += 256) {
        float x = kb[3 * m + 0];
        float y = kb[3 * m + 1];
        float z = kb[3 * m + 2];
        skx[m] = x; sky[m] = y; skz[m] = z;
        skn[m] = norm_noFMA(x, y, z);   // primary-path ||k||^2 (also filter seed)
    }
    __syncthreads();

    const int q0 = blockIdx.x * 512 + threadIdx.x;   // and q0 + 256
    float uxq[2], uyq[2], uzq[2];
    unsigned long long ax2[2], ay2[2], az2[2];
#pragma unroll
    for (int t = 0; t < 2; ++t) {
        const float* u = unknown + ((size_t)b * NQ + q0 + t * 256) * 3;
        uxq[t] = u[0]; uyq[t] = u[1]; uzq[t] = u[2];
        ax2[t] = pack2(-2.f * uxq[t], -2.f * uxq[t]);
        ay2[t] = pack2(-2.f * uyq[t], -2.f * uyq[t]);
        az2[t] = pack2(-2.f * uzq[t], -2.f * uzq[t]);
    }

    // top-4 on the fast packed score per query; refined in the epilogue.
    float c0[2] = {3.4e38f, 3.4e38f}, c1[2] = {3.4e38f, 3.4e38f};
    float c2[2] = {3.4e38f, 3.4e38f}, c3[2] = {3.4e38f, 3.4e38f};
    int   i0[2] = {0, 0}, i1[2] = {0, 0}, i2[2] = {0, 0}, i3[2] = {0, 0};

    const double2* X  = (const double2*)skx;
    const double2* Y  = (const double2*)sky;
    const double2* Z  = (const double2*)skz;
    const double2* Nn = (const double2*)skn;

#pragma unroll 2
    for (int p = 0; p < MK / 4; ++p) {
        double2 xv = X[p], yv = Y[p], zv = Z[p], nv = Nn[p];
        unsigned long long x01 = __double_as_longlong(xv.x);
        unsigned long long x23 = __double_as_longlong(xv.y);
        unsigned long long y01 = __double_as_longlong(yv.x);
        unsigned long long y23 = __double_as_longlong(yv.y);
        unsigned long long z01 = __double_as_longlong(zv.x);
        unsigned long long z23 = __double_as_longlong(zv.y);
        unsigned long long n01 = __double_as_longlong(nv.x);
        unsigned long long n23 = __double_as_longlong(nv.y);

#pragma unroll
        for (int tq = 0; tq < 2; ++tq) {
            unsigned long long s01 =
                fma2(az2[tq], z01, fma2(ay2[tq], y01, fma2(ax2[tq], x01, n01)));
            unsigned long long s23 =
                fma2(az2[tq], z23, fma2(ay2[tq], y23, fma2(ax2[tq], x23, n23)));

            float s0, s1, s2, s3;
            unpack2(s01, s0, s1);
            unpack2(s23, s2, s3);
            float mn = fminf(fminf(s0, s1), fminf(s2, s3));
            if (mn < c3[tq]) {
                // FLAT predicated top-4 update, order s0..s3; strict '<'
                // keeps earlier index on ties.
                const int j = 4 * p;
#pragma unroll
                for (int t = 0; t < 4; ++t) {
                    const float s = (t == 0) ? s0 : (t == 1) ? s1
                                  : (t == 2) ? s2 : s3;
                    const int jt = j + t;
                    const bool p3 = s < c3[tq];
                    const bool p2 = s < c2[tq];
                    const bool p1 = s < c1[tq];
                    const bool p0 = s < c0[tq];
                    const float nc3 = p2 ? c2[tq] : s;  const int ni3 = p2 ? i2[tq] : jt;
                    c3[tq] = p3 ? nc3 : c3[tq];         i3[tq] = p3 ? ni3 : i3[tq];
                    const float nc2 = p1 ? c1[tq] : s;  const int ni2 = p1 ? i1[tq] : jt;
                    c2[tq] = p2 ? nc2 : c2[tq];         i2[tq] = p2 ? ni2 : i2[tq];
                    const float nc1 = p0 ? c0[tq] : s;  const int ni1 = p0 ? i0[tq] : jt;
                    c1[tq] = p1 ? nc1 : c1[tq];         i1[tq] = p1 ? ni1 : i1[tq];
                    c0[tq] = p0 ? s : c0[tq];           i0[tq] = p0 ? jt : i0[tq];
                }
            }
        }
    }

#pragma unroll
    for (int tq = 0; tq < 2; ++tq)
        finish_query(b, q0 + tq * 256, uxq[tq], uyq[tq], uzq[tq],
                     skx, sky, skz, skn,
                     c0[tq], c1[tq], c2[tq], c3[tq],
                     i0[tq], i1[tq], i2[tq], i3[tq]);
}

// ---------------- Kernel 2: weighted interpolation (v3) ------------------
// grid (CF/CC, B, SPLITS), 1024 threads. smem: feats chunk only (192 KB).
// Warp = 32 consecutive queries x one channel-quad: every STG.32 is a full
// 128B coalesced run. idx/w read directly from gmem (coalesced LDG.128,
// 2x redundancy absorbed by L1). No barriers inside the tile loop -> unroll
// batches independent LDG+LDS chains for MLP.
#define CC     8
#define PADW   12
#define SPLITS 2
#define QT     512

extern "C" __global__ void __launch_bounds__(1024, 1)
interp_k(const float* __restrict__ feats, float* __restrict__ out) {
    extern __shared__ float sf[];                 // [MK][PADW]

    const int tid   = threadIdx.x;
    const int chunk = blockIdx.x;
    const int b     = blockIdx.y;
    const int sp    = blockIdx.z;
    const int c0    = chunk * CC;

    // load 8 feature rows into channel-minor padded layout
    const float* fb = feats + ((size_t)b * CF + c0) * MK;
#pragma unroll
    for (int cc = 0; cc < CC; ++cc) {
        const float* row = fb + (size_t)cc * MK;
        for (int m = tid; m < MK; m += 1024)
            sf[m * PADW + cc] = row[m];
    }
    __syncthreads();   // the only barrier

    const int qp    = tid & (QT - 1);        // query slot in tile
    const int cc4   = (tid >> 9) * 4;        // channel-quad 0 or 4
    const int qbase = sp * (NQ / SPLITS);
    const int iobase = b * NQ + qbase;
    float* outb = out + ((size_t)(b * CF + c0 + cc4)) * NQ;

#pragma unroll 2
    for (int tile = 0; tile < (NQ / SPLITS) / QT; ++tile) {
        const int qi = tile * QT + qp;
        const int4   I = __ldg(&g_idx[iobase + qi]);
        const float4 W = __ldg(&g_w[iobase + qi]);
        const int q = qbase + qi;

        const float4 f0 = *(const float4*)&sf[I.x * PADW + cc4];
        const float4 f1 = *(const float4*)&sf[I.y * PADW + cc4];
        const float4 f2 = *(const float4*)&sf[I.z * PADW + cc4];

        float4 v;
        v.x = fmaf(W.z, f2.x, fmaf(W.y, f1.x, W.x * f0.x));
        v.y = fmaf(W.z, f2.y, fmaf(W.y, f1.y, W.x * f0.y));
        v.z = fmaf(W.z, f2.z, fmaf(W.y, f1.z, W.x * f0.z));
        v.w = fmaf(W.z, f2.w, fmaf(W.y, f1.w, W.x * f0.w));

        if (__any_sync(0xffffffffu, W.w != 0.f)) {   // rare hedge path
            const float4 f3 = *(const float4*)&sf[I.w * PADW + cc4];
            v.x = fmaf(W.w, f3.x, v.x);
            v.y = fmaf(W.w, f3.y, v.y);
            v.z = fmaf(W.w, f3.z, v.z);
            v.w = fmaf(W.w, f3.w, v.w);
        }

        outb[0 * NQ + q] = v.x;
        outb[1 * NQ + q] = v.y;
        outb[2 * NQ + q] = v.z;
        outb[3 * NQ + q] = v.w;
    }
}

// ---------------- launch ----------------
extern "C" void kernel_launch(void* const* d_in, const int* in_sizes, int n_in,
                              void* d_out, int out_size) {
    const float* unknown = (const float*)d_in[0];  // [B, N, 3]
    const float* known   = (const float*)d_in[1];  // [B, M, 3]
    const float* feats   = (const float*)d_in[2];  // [B, C, M]
    float* out = (float*)d_out;                    // [B, C, N]

    (void)in_sizes; (void)n_in; (void)out_size;

    const int smem1 = 4 * MK * (int)sizeof(float);        // 64 KB
    const int smem2 = MK * PADW * (int)sizeof(float);     // 192 KB
    cudaFuncSetAttribute(three_nn_k, cudaFuncAttributeMaxDynamicSharedMemorySize, smem1);
    cudaFuncSetAttribute(interp_k,   cudaFuncAttributeMaxDynamicSharedMemorySize, smem2);

    three_nn_k<<<dim3(NQ / 512, B_), 256, smem1>>>(unknown, known);
    interp_k<<<dim3(CF / CC, B_, SPLITS), 1024, smem2>>>(feats, out);
}

// round 17
// speedup vs baseline: 1.0157x; 1.0157x over previous
#include <cuda_runtime.h>
#include <cstdint>

#define B_    8
#define NQ    16384
#define MK    4096
#define CF    256
#define EPSV  1e-8f

// Scratch: per-query 4 candidate indices and 4 weights (3rd weight split
// across the 3rd/4th nearest when plausible fp32 paths disagree).
__device__ int4   g_idx[B_ * NQ];
__device__ float4 g_w[B_ * NQ];

// ---------------- packed f32x2 helpers (Blackwell) ----------------
__device__ __forceinline__ unsigned long long fma2(unsigned long long a,
                                                   unsigned long long b,
                                                   unsigned long long c) {
    unsigned long long d;
    asm("fma.rn.f32x2 %0, %1, %2, %3;" : "=l"(d) : "l"(a), "l"(b), "l"(c));
    return d;
}
__device__ __forceinline__ unsigned long long pack2(float lo, float hi) {
    unsigned long long d;
    asm("mov.b64 %0, {%1, %2};" : "=l"(d) : "f"(lo), "f"(hi));
    return d;
}
__device__ __forceinline__ void unpack2(unsigned long long v, float& lo, float& hi) {
    asm("mov.b64 {%0, %1}, %2;" : "=f"(lo), "=f"(hi) : "l"(v));
}

// ---------------- rounding-path variants ----------------
__device__ __forceinline__ float norm_noFMA(float x, float y, float z) {
    return __fadd_rn(__fadd_rn(__fmul_rn(x, x), __fmul_rn(y, y)), __fmul_rn(z, z));
}
__device__ __forceinline__ float norm_fx(float x, float y, float z) {  // x bare
    return __fmaf_rn(z, z, __fmaf_rn(y, y, __fmul_rn(x, x)));
}
__device__ __forceinline__ float norm_fy(float x, float y, float z) {  // y bare
    return __fmaf_rn(z, z, __fmaf_rn(x, x, __fmul_rn(y, y)));
}
__device__ __forceinline__ float norm_fz(float x, float y, float z) {  // z bare
    return __fmaf_rn(x, x, __fmaf_rn(y, y, __fmul_rn(z, z)));
}

// Primary path (cublas-style): dot = fma(uz,kz, fma(uy,ky, rn(ux*kx)));
// d2 = rn( rn(un+kn) - 2*dot ), norms noFMA.
__device__ __forceinline__ float d2_primary(float ux, float uy, float uz, float un3,
                                            float kx, float ky, float kz, float kn3) {
    float t = __fmaf_rn(uz, kz, __fmaf_rn(uy, ky, __fmul_rn(ux, kx)));
    return __fsub_rn(__fadd_rn(un3, kn3), __fadd_rn(t, t));
}

// ---------------- per-query epilogue (unchanged numerics) ----------------
// primary order + 12-path disagreement hedge; writes g_idx/g_w.
__device__ __forceinline__ void finish_query(
    int b, int q, float ux, float uy, float uz,
    const float* skx, const float* sky, const float* skz, const float* skn,
    float c0, float c1, float c2, float c3, int i0, int i1, int i2, int i3) {

    int fi[4] = { i0, i1, i2, i3 };
    float kxs[4], kys[4], kzs[4], kn3s[4], d2p[4];
    const float un3 = norm_noFMA(ux, uy, uz);
#pragma unroll
    for (int t = 0; t < 4; ++t) {
        kxs[t] = skx[fi[t]]; kys[t] = sky[fi[t]]; kzs[t] = skz[fi[t]];
        kn3s[t] = skn[fi[t]];
        d2p[t] = d2_primary(ux, uy, uz, un3, kxs[t], kys[t], kzs[t], kn3s[t]);
    }
    // stable sort-4 by (primary d2, idx) — matches top_k tie semantics
#define CSWAP(a, b_)                                                        \
    if (d2p[a] > d2p[b_] || (d2p[a] == d2p[b_] && fi[a] > fi[b_])) {        \
        float td = d2p[a]; d2p[a] = d2p[b_]; d2p[b_] = td;                  \
        int ti = fi[a]; fi[a] = fi[b_]; fi[b_] = ti;                        \
        td = kxs[a]; kxs[a] = kxs[b_]; kxs[b_] = td;                        \
        td = kys[a]; kys[a] = kys[b_]; kys[b_] = td;                        \
        td = kzs[a]; kzs[a] = kzs[b_]; kzs[b_] = td;                        \
        td = kn3s[a]; kn3s[a] = kn3s[b_]; kn3s[b_] = td;                    \
    }
    CSWAP(0, 1) CSWAP(2, 3) CSWAP(0, 2) CSWAP(1, 3) CSWAP(1, 2)
#undef CSWAP

    // 12 alternative-path d2 values for the boundary pair (slots 2 and 3)
    const float unx = norm_fx(ux, uy, uz);
    const float uny = norm_fy(ux, uy, uz);
    const float m2x = -2.f * ux, m2y = -2.f * uy, m2z = -2.f * uz;
    float pv[2][12];
#pragma unroll
    for (int t = 0; t < 2; ++t) {
        const float kx = kxs[2 + t], ky = kys[2 + t], kz = kzs[2 + t];
        const float knx = norm_fx(kx, ky, kz);
        const float kny = norm_fy(kx, ky, kz);
        const float kn3 = kn3s[2 + t];
        const float knz = norm_fz(kx, ky, kz);
        const float t1 = __fmaf_rn(uz, kz, __fmaf_rn(uy, ky, __fmul_rn(ux, kx)));
        const float t2 = __fmaf_rn(uz, kz, __fmaf_rn(ux, kx, __fmul_rn(uy, ky)));
        const float t3 = __fadd_rn(__fadd_rn(__fmul_rn(ux, kx), __fmul_rn(uy, ky)),
                                   __fmul_rn(uz, kz));
        const float nn[3] = { __fadd_rn(unx, knx), __fadd_rn(uny, kny),
                              __fadd_rn(norm_noFMA(ux, uy, uz), kn3) };
        const float dd[3] = { __fadd_rn(t1, t1), __fadd_rn(t2, t2),
                              __fadd_rn(t3, t3) };
#pragma unroll
        for (int a = 0; a < 3; ++a)
#pragma unroll
            for (int c = 0; c < 3; ++c)
                pv[t][a * 3 + c] = __fsub_rn(nn[c], dd[a]);
        // fused-chain variants (R1 family) — compare by s (common un offset)
        pv[t][9]  = __fmaf_rn(m2z, kz, __fmaf_rn(m2y, ky, __fmaf_rn(m2x, kx, knz)));
        pv[t][10] = __fmaf_rn(m2x, kx, __fmaf_rn(m2y, ky, __fmaf_rn(m2z, kz, knz)));
        pv[t][11] = __fmaf_rn(m2z, kz, __fmaf_rn(m2y, ky, __fmaf_rn(m2x, kx, kn3)));
    }
    bool hedge = false;
#pragma unroll
    for (int v = 0; v < 12; ++v)
        hedge |= (pv[1][v] < pv[0][v]) ||
                 (pv[1][v] == pv[0][v] && fi[3] < fi[2]);
    // insurance: primary gap below ~0.5 ulp of the cancelling magnitude
    const float gap = d2p[3] - d2p[2];
    hedge |= (gap < __fadd_rn(un3, kn3s[2]) * 3.0e-8f);
    const float p = hedge ? 0.5f : 0.0f;

    const float r0 = __fdiv_rn(1.f, __fadd_rn(d2p[0], EPSV));
    const float r1 = __fdiv_rn(1.f, __fadd_rn(d2p[1], EPSV));
    const float r2 = __fdiv_rn(1.f, __fadd_rn(d2p[2], EPSV));
    const float nrm = __fadd_rn(__fadd_rn(r0, r1), r2);
    const float w2 = __fdiv_rn(r2, nrm);

    const int o = b * NQ + q;
    g_idx[o] = make_int4(fi[0], fi[1], fi[2], fi[3]);
    g_w[o]   = make_float4(__fdiv_rn(r0, nrm), __fdiv_rn(r1, nrm),
                           w2 * (1.f - p), w2 * p);
}

// Flat predicated top-4 update for one candidate (s, jt) on query slot tq.
// Strict '<' keeps earlier index on ties — identical state evolution to the
// original insert chain.
#define UPD(tq, s, jt) do {                                                  \
    const bool p3 = (s) < c3[tq];                                            \
    const bool p2 = (s) < c2[tq];                                            \
    const bool p1 = (s) < c1[tq];                                            \
    const bool p0 = (s) < c0[tq];                                            \
    const float nc3 = p2 ? c2[tq] : (s);  const int ni3 = p2 ? i2[tq] : (jt);\
    c3[tq] = p3 ? nc3 : c3[tq];           i3[tq] = p3 ? ni3 : i3[tq];        \
    const float nc2 = p1 ? c1[tq] : (s);  const int ni2 = p1 ? i1[tq] : (jt);\
    c2[tq] = p2 ? nc2 : c2[tq];           i2[tq] = p2 ? ni2 : i2[tq];        \
    const float nc1 = p0 ? c0[tq] : (s);  const int ni1 = p0 ? i0[tq] : (jt);\
    c1[tq] = p1 ? nc1 : c1[tq];           i1[tq] = p1 ? ni1 : i1[tq];        \
    c0[tq] = p0 ? (s) : c0[tq];           i0[tq] = p0 ? (jt) : i0[tq];       \
} while (0)

// ---------------- Kernel 1: three_nn, 2 queries per thread ----------------
// grid (NQ/512, B), 256 threads. Pair-granular guards (g=2): region count
// grows only ~log vs g=4 while region cost halves -> less warp-uniform
// insert work.
extern "C" __global__ void __launch_bounds__(256, 1)
three_nn_k(const float* __restrict__ unknown, const float* __restrict__ known) {
    extern __shared__ float sh[];
    float* skx = sh;
    float* sky = sh + MK;
    float* skz = sh + 2 * MK;
    float* skn = sh + 3 * MK;

    const int b = blockIdx.y;
    const float* kb = known + (size_t)b * MK * 3;
    for (int m = threadIdx.x; m < MK; m += 256) {
        float x = kb[3 * m + 0];
        float y = kb[3 * m + 1];
        float z = kb[3 * m + 2];
        skx[m] = x; sky[m] = y; skz[m] = z;
        skn[m] = norm_noFMA(x, y, z);   // primary-path ||k||^2 (also filter seed)
    }
    __syncthreads();

    const int q0 = blockIdx.x * 512 + threadIdx.x;   // and q0 + 256
    float uxq[2], uyq[2], uzq[2];
    unsigned long long ax2[2], ay2[2], az2[2];
#pragma unroll
    for (int t = 0; t < 2; ++t) {
        const float* u = unknown + ((size_t)b * NQ + q0 + t * 256) * 3;
        uxq[t] = u[0]; uyq[t] = u[1]; uzq[t] = u[2];
        ax2[t] = pack2(-2.f * uxq[t], -2.f * uxq[t]);
        ay2[t] = pack2(-2.f * uyq[t], -2.f * uyq[t]);
        az2[t] = pack2(-2.f * uzq[t], -2.f * uzq[t]);
    }

    // top-4 on the fast packed score per query; refined in the epilogue.
    float c0[2] = {3.4e38f, 3.4e38f}, c1[2] = {3.4e38f, 3.4e38f};
    float c2[2] = {3.4e38f, 3.4e38f}, c3[2] = {3.4e38f, 3.4e38f};
    int   i0[2] = {0, 0}, i1[2] = {0, 0}, i2[2] = {0, 0}, i3[2] = {0, 0};

    const double2* X  = (const double2*)skx;
    const double2* Y  = (const double2*)sky;
    const double2* Z  = (const double2*)skz;
    const double2* Nn = (const double2*)skn;

#pragma unroll 2
    for (int p = 0; p < MK / 4; ++p) {
        double2 xv = X[p], yv = Y[p], zv = Z[p], nv = Nn[p];
        unsigned long long x01 = __double_as_longlong(xv.x);
        unsigned long long x23 = __double_as_longlong(xv.y);
        unsigned long long y01 = __double_as_longlong(yv.x);
        unsigned long long y23 = __double_as_longlong(yv.y);
        unsigned long long z01 = __double_as_longlong(zv.x);
        unsigned long long z23 = __double_as_longlong(zv.y);
        unsigned long long n01 = __double_as_longlong(nv.x);
        unsigned long long n23 = __double_as_longlong(nv.y);

#pragma unroll
        for (int tq = 0; tq < 2; ++tq) {
            unsigned long long s01 =
                fma2(az2[tq], z01, fma2(ay2[tq], y01, fma2(ax2[tq], x01, n01)));
            unsigned long long s23 =
                fma2(az2[tq], z23, fma2(ay2[tq], y23, fma2(ax2[tq], x23, n23)));

            float s0, s1, s2, s3;
            unpack2(s01, s0, s1);
            unpack2(s23, s2, s3);
            const int j = 4 * p;
            if (fminf(s0, s1) < c3[tq]) {   // pair guard 0
                UPD(tq, s0, j + 0);
                UPD(tq, s1, j + 1);
            }
            if (fminf(s2, s3) < c3[tq]) {   // pair guard 1
                UPD(tq, s2, j + 2);
                UPD(tq, s3, j + 3);
            }
        }
    }

#pragma unroll
    for (int tq = 0; tq < 2; ++tq)
        finish_query(b, q0 + tq * 256, uxq[tq], uyq[tq], uzq[tq],
                     skx, sky, skz, skn,
                     c0[tq], c1[tq], c2[tq], c3[tq],
                     i0[tq], i1[tq], i2[tq], i3[tq]);
}

// ---------------- Kernel 2: weighted interpolation (v3) ------------------
// grid (CF/CC, B, SPLITS), 1024 threads. smem: feats chunk only (192 KB).
// SPLITS=4: 1024 blocks -> ~7 blocks/SM sequence, makespan 3.5 half-waves
// vs 4 full waves at SPLITS=2 (tail quantization ~12% saved).
#define CC     8
#define PADW   12
#define SPLITS 4
#define QT     512

extern "C" __global__ void __launch_bounds__(1024, 1)
interp_k(const float* __restrict__ feats, float* __restrict__ out) {
    extern __shared__ float sf[];                 // [MK][PADW]

    const int tid   = threadIdx.x;
    const int chunk = blockIdx.x;
    const int b     = blockIdx.y;
    const int sp    = blockIdx.z;
    const int c0    = chunk * CC;

    // load 8 feature rows into channel-minor padded layout
    const float* fb = feats + ((size_t)b * CF + c0) * MK;
#pragma unroll
    for (int cc = 0; cc < CC; ++cc) {
        const float* row = fb + (size_t)cc * MK;
        for (int m = tid; m < MK; m += 1024)
            sf[m * PADW + cc] = row[m];
    }
    __syncthreads();   // the only barrier

    const int qp    = tid & (QT - 1);        // query slot in tile
    const int cc4   = (tid >> 9) * 4;        // channel-quad 0 or 4
    const int qbase = sp * (NQ / SPLITS);
    const int iobase = b * NQ + qbase;
    float* outb = out + ((size_t)(b * CF + c0 + cc4)) * NQ;

#pragma unroll 2
    for (int tile = 0; tile < (NQ / SPLITS) / QT; ++tile) {
        const int qi = tile * QT + qp;
        const int4   I = __ldg(&g_idx[iobase + qi]);
        const float4 W = __ldg(&g_w[iobase + qi]);
        const int q = qbase + qi;

        const float4 f0 = *(const float4*)&sf[I.x * PADW + cc4];
        const float4 f1 = *(const float4*)&sf[I.y * PADW + cc4];
        const float4 f2 = *(const float4*)&sf[I.z * PADW + cc4];

        float4 v;
        v.x = fmaf(W.z, f2.x, fmaf(W.y, f1.x, W.x * f0.x));
        v.y = fmaf(W.z, f2.y, fmaf(W.y, f1.y, W.x * f0.y));
        v.z = fmaf(W.z, f2.z, fmaf(W.y, f1.z, W.x * f0.z));
        v.w = fmaf(W.z, f2.w, fmaf(W.y, f1.w, W.x * f0.w));

        if (__any_sync(0xffffffffu, W.w != 0.f)) {   // rare hedge path
            const float4 f3 = *(const float4*)&sf[I.w * PADW + cc4];
            v.x = fmaf(W.w, f3.x, v.x);
            v.y = fmaf(W.w, f3.y, v.y);
            v.z = fmaf(W.w, f3.z, v.z);
            v.w = fmaf(W.w, f3.w, v.w);
        }

        outb[0 * NQ + q] = v.x;
        outb[1 * NQ + q] = v.y;
        outb[2 * NQ + q] = v.z;
        outb[3 * NQ + q] = v.w;
    }
}

// ---------------- launch ----------------
extern "C" void kernel_launch(void* const* d_in, const int* in_sizes, int n_in,
                              void* d_out, int out_size) {
    const float* unknown = (const float*)d_in[0];  // [B, N, 3]
    const float* known   = (const float*)d_in[1];  // [B, M, 3]
    const float* feats   = (const float*)d_in[2];  // [B, C, M]
    float* out = (float*)d_out;                    // [B, C, N]

    (void)in_sizes; (void)n_in; (void)out_size;

    const int smem1 = 4 * MK * (int)sizeof(float);        // 64 KB
    const int smem2 = MK * PADW * (int)sizeof(float);     // 192 KB
    cudaFuncSetAttribute(three_nn_k, cudaFuncAttributeMaxDynamicSharedMemorySize, smem1);
    cudaFuncSetAttribute(interp_k,   cudaFuncAttributeMaxDynamicSharedMemorySize, smem2);

    three_nn_k<<<dim3(NQ / 512, B_), 256, smem1>>>(unknown, known);
    interp_k<<<dim3(CF / CC, B_, SPLITS), 1024, smem2>>>(feats, out);
}